// round 4
// baseline (speedup 1.0000x reference)
#include <cuda_runtime.h>
#include <cstdint>

// LSTM B=128, T=2048, F=3, U=256. 16 clusters x 8 CTAs. Each CTA: 8 batch rows x 32 units.
// R3: h exchange via DSMEM st.async + mbarrier complete_tx (no global atomics/fences/spins).
// Producers push {h,h} b64 pairs straight into all 8 peers' receive buffers (FFMA2 layout),
// consumer wakes on local mbarrier and feeds the GEMM with zero staging.

#define BB 128
#define TT 2048
#define FF 3
#define UU 256
#define G4 1024
#define NCTA 128
#define NTHR 256
#define CLUSTER 8

// SMEM layout (float offsets)
#define OFF_WH   0        // 256*128 = 32768   permuted Wh slice [k][u_l*4+gate]
#define OFF_HB0  32768    // 8*516   = 4128    recv buf ping: [b][2k]={h,h}, stride 516
#define OFF_HB1  36896    // 4128              recv buf pong
#define OFF_BIAS 41024    // 128
#define OFF_WX   41152    // 384
#define OFF_XS   41536    // 64  (x tile, double-buffered by step parity)
#define OFF_MBAR 41600    // 2 x 8B mbarriers
#define SMEM_FLOATS 41608
#define SMEM_BYTES (SMEM_FLOATS * 4)
#define HSTRIDE 516
#define HBUF_DELTA_B ((OFF_HB1 - OFF_HB0) * 4)   // 16512 bytes
#define TX_BYTES 16384                            // 8 producers * 256 thr * 8B

__device__ __forceinline__ float sig_f(float x) {
    x = fminf(fmaxf(x, -30.f), 30.f);
    float e = __expf(-x);
    return __fdividef(1.f, 1.f + e);
}

__device__ __forceinline__ float tanh_f(float x) {
    float ax = fminf(fabsf(x), 15.f);
    float e = __expf(-2.f * ax);
    float r = __fdividef(1.f - e, 1.f + e);
    return copysignf(r, x);
}

__device__ __forceinline__ void ffma2(unsigned long long& acc,
                                      unsigned long long a,
                                      unsigned long long b) {
    asm("fma.rn.f32x2 %0, %1, %2, %0;" : "+l"(acc) : "l"(a), "l"(b));
}

__device__ __forceinline__ void mbar_init(uint32_t addr, uint32_t cnt) {
    asm volatile("mbarrier.init.shared.b64 [%0], %1;" :: "r"(addr), "r"(cnt) : "memory");
}
__device__ __forceinline__ void mbar_arrive_expect_tx(uint32_t addr, uint32_t tx) {
    asm volatile("mbarrier.arrive.expect_tx.shared.b64 _, [%0], %1;"
                 :: "r"(addr), "r"(tx) : "memory");
}
__device__ __forceinline__ void mbar_wait(uint32_t addr, uint32_t parity) {
    uint32_t done;
    asm volatile(
        "{\n\t.reg .pred p;\n\t"
        "mbarrier.try_wait.parity.acquire.cta.shared::cta.b64 p, [%1], %2;\n\t"
        "selp.b32 %0, 1, 0, p;\n\t}"
        : "=r"(done) : "r"(addr), "r"(parity) : "memory");
    if (!done) {
        asm volatile(
            "{\n\t.reg .pred P1;\n\t"
            "WAIT_LOOP_%=:\n\t"
            "mbarrier.try_wait.parity.acquire.cta.shared::cta.b64 P1, [%0], %1, 0x989680;\n\t"
            "@P1 bra.uni WAIT_DONE_%=;\n\t"
            "bra.uni WAIT_LOOP_%=;\n\t"
            "WAIT_DONE_%=:\n\t}"
            :: "r"(addr), "r"(parity) : "memory");
    }
}
__device__ __forceinline__ void st_async_b64(uint32_t dst, unsigned long long v, uint32_t mbar) {
    asm volatile(
        "st.async.shared::cluster.mbarrier::complete_tx::bytes.b64 [%0], %1, [%2];"
        :: "r"(dst), "l"(v), "r"(mbar) : "memory");
}

__global__ void __launch_bounds__(NTHR, 1) __cluster_dims__(CLUSTER, 1, 1)
lstm_persistent_kernel(
    const float* __restrict__ x,     // [B, T, F]
    const float* __restrict__ Wx,    // [F, 4U]
    const float* __restrict__ Wh,    // [U, 4U]
    const float* __restrict__ bias,  // [4U]
    float* __restrict__ out,         // ys [B,T,U] (+ h_T, c_T if write_hc)
    int write_hc)
{
    extern __shared__ float sm[];
    float* whs = sm + OFF_WH;
    float* bs  = sm + OFF_BIAS;
    float* wxs = sm + OFF_WX;
    float* xs  = sm + OFF_XS;

    const int tid = threadIdx.x;
    const int RB  = blockIdx.x >> 3;   // cluster id 0..15
    const int CB  = blockIdx.x & 7;    // rank in cluster = gate-column block
    const int gb  = RB * 8;            // global batch base

    const uint32_t smem_u32 = (uint32_t)__cvta_generic_to_shared(sm);
    const uint32_t mbar0 = smem_u32 + OFF_MBAR * 4;      // used by steps 2,4,...
    const uint32_t mbar1 = mbar0 + 8;                    // used by steps 1,3,...

    // ---------------- setup: permuted weights -> SMEM ----------------
    #pragma unroll
    for (int g = 0; g < 4; g++) {
        const int gbase = g * UU + CB * 32;
        for (int i = tid; i < 256 * 32; i += NTHR) {
            int k = i >> 5, ul = i & 31;
            whs[k * 128 + ul * 4 + g] = Wh[k * G4 + gbase + ul];
        }
        for (int i = tid; i < 3 * 32; i += NTHR) {
            int f = i >> 5, ul = i & 31;
            wxs[f * 128 + ul * 4 + g] = Wx[f * G4 + gbase + ul];
        }
    }
    if (tid < 128) {
        int ul = tid >> 2, g = tid & 3;
        bs[tid] = bias[g * UU + CB * 32 + ul];
    }
    // zero both receive buffers (step 0 reads hbuf0 as h=0)
    for (int i = tid; i < 2 * 8 * HSTRIDE; i += NTHR)
        sm[OFF_HB0 + i] = 0.f;

    // mbarriers: count=1; arm bar1 (first use: step 1) and bar0 (first use: step 2)
    if (tid == 0) {
        mbar_init(mbar0, 1);
        mbar_init(mbar1, 1);
        mbar_arrive_expect_tx(mbar0, TX_BYTES);
        mbar_arrive_expect_tx(mbar1, TX_BYTES);
    }

    // per-rank cluster base addresses for sends
    uint32_t r_base[CLUSTER];
    #pragma unroll
    for (int r = 0; r < CLUSTER; r++)
        asm("mapa.shared::cluster.u32 %0, %1, %2;"
            : "=r"(r_base[r]) : "r"(smem_u32), "r"(r));

    const int u_l = tid >> 3;   // 0..31
    const int b_l = tid & 7;    // 0..7
    const int gcol = CB * 32 + u_l;
    // my slot byte offset inside a receive buffer: [b_l][2*gcol] (8B pair)
    const uint32_t slot_off = (uint32_t)(OFF_HB0 * 4 + b_l * HSTRIDE * 4 + gcol * 8);

    float c = 0.f;
    float xpre = 0.f;
    if (tid < 24) xpre = __ldg(&x[(size_t)(gb + tid / 3) * (TT * FF) + tid % 3]);

    __syncthreads();
    asm volatile("barrier.cluster.arrive.aligned;" ::: "memory");
    asm volatile("barrier.cluster.wait.aligned;"   ::: "memory");

    int ph0 = 0, ph1 = 0;

    for (int s = 0; s < TT; s++) {
        const int p = s & 1;
        if (tid < 24) xs[p * 32 + tid] = xpre;

        // -------- wait for this step's h, re-arm barrier for step s+2 --------
        if (s > 0) {
            if (p) { mbar_wait(mbar1, ph1); ph1 ^= 1; }
            else   { mbar_wait(mbar0, ph0); ph0 ^= 1; }
            if (tid == 0) mbar_arrive_expect_tx(p ? mbar1 : mbar0, TX_BYTES);
        }
        __syncthreads();   // data-ready + re-arm ordered before everyone's sends

        // -------- acc init: bias + x @ Wx --------
        float a0, a1, a2, a3;
        {
            float4 bb4 = *reinterpret_cast<const float4*>(bs + u_l * 4);
            a0 = bb4.x; a1 = bb4.y; a2 = bb4.z; a3 = bb4.w;
            float xv0 = xs[p * 32 + b_l * 3 + 0];
            float xv1 = xs[p * 32 + b_l * 3 + 1];
            float xv2 = xs[p * 32 + b_l * 3 + 2];
            float4 w;
            w = *reinterpret_cast<const float4*>(wxs + 0 * 128 + u_l * 4);
            a0 = fmaf(xv0, w.x, a0); a1 = fmaf(xv0, w.y, a1);
            a2 = fmaf(xv0, w.z, a2); a3 = fmaf(xv0, w.w, a3);
            w = *reinterpret_cast<const float4*>(wxs + 1 * 128 + u_l * 4);
            a0 = fmaf(xv1, w.x, a0); a1 = fmaf(xv1, w.y, a1);
            a2 = fmaf(xv1, w.z, a2); a3 = fmaf(xv1, w.w, a3);
            w = *reinterpret_cast<const float4*>(wxs + 2 * 128 + u_l * 4);
            a0 = fmaf(xv2, w.x, a0); a1 = fmaf(xv2, w.y, a1);
            a2 = fmaf(xv2, w.z, a2); a3 = fmaf(xv2, w.w, a3);
        }

        // prefetch next x
        if (tid < 24 && s + 1 < TT)
            xpre = __ldg(&x[(size_t)(gb + tid / 3) * (TT * FF) + (size_t)(s + 1) * FF + tid % 3]);

        // -------- GEMM: z += h @ Wh, packed f32x2, K=256, zero staging --------
        unsigned long long a01, a23;
        asm("mov.b64 %0, {%1, %2};" : "=l"(a01) : "f"(a0), "f"(a1));
        asm("mov.b64 %0, {%1, %2};" : "=l"(a23) : "f"(a2), "f"(a3));
        {
            const float* whp = whs + u_l * 4;
            const unsigned long long* hp = reinterpret_cast<const unsigned long long*>(
                sm + OFF_HB0 + p * (8 * HSTRIDE) + b_l * HSTRIDE);
            #pragma unroll 8
            for (int k = 0; k < UU; k++) {
                ulonglong2 wv = *reinterpret_cast<const ulonglong2*>(whp + k * 128);
                unsigned long long hv = hp[k];
                ffma2(a01, hv, wv.x);
                ffma2(a23, hv, wv.y);
            }
        }
        asm("mov.b64 {%0, %1}, %2;" : "=f"(a0), "=f"(a1) : "l"(a01));
        asm("mov.b64 {%0, %1}, %2;" : "=f"(a2), "=f"(a3) : "l"(a23));

        // -------- gates / state / outputs --------
        float hn;
        {
            float ig = sig_f(a0);
            float fg = sig_f(a1);
            float gg = tanh_f(a2);
            float og = sig_f(a3);
            c = fmaf(fg, c, ig * gg);
            hn = og * tanh_f(c);
            out[(size_t)(gb + b_l) * (TT * UU) + (size_t)s * UU + gcol] = hn;
            if (s == TT - 1 && write_hc) {
                out[(size_t)BB * TT * UU + (size_t)(gb + b_l) * UU + gcol] = hn;
                out[(size_t)BB * TT * UU + (size_t)BB * UU + (size_t)(gb + b_l) * UU + gcol] = c;
            }
        }

        // -------- push {hn,hn} to all 8 cluster CTAs' next-parity buffers --------
        if (s + 1 < TT) {
            const uint32_t pn = (uint32_t)((s + 1) & 1);
            unsigned long long pair;
            asm("mov.b64 %0, {%1, %1};" : "=l"(pair) : "f"(hn));
            const uint32_t doff = slot_off + pn * HBUF_DELTA_B;
            const uint32_t moff = (uint32_t)(OFF_MBAR * 4) + pn * 8;
            #pragma unroll
            for (int r = 0; r < CLUSTER; r++)
                st_async_b64(r_base[r] + doff, pair, r_base[r] + moff);
        }
    }

    // no CTA may exit while peers could still touch its SMEM
    asm volatile("barrier.cluster.arrive.aligned;" ::: "memory");
    asm volatile("barrier.cluster.wait.aligned;"   ::: "memory");
}

extern "C" void kernel_launch(void* const* d_in, const int* in_sizes, int n_in,
                              void* d_out, int out_size) {
    const float* x    = (const float*)d_in[0];
    const float* Wx   = (const float*)d_in[1];
    const float* Wh   = (const float*)d_in[2];
    const float* bias = (const float*)d_in[3];
    float* out = (float*)d_out;

    long long need = (long long)BB * TT * UU + 2LL * BB * UU;
    int write_hc = ((long long)out_size >= need) ? 1 : 0;

    cudaFuncSetAttribute(lstm_persistent_kernel,
                         cudaFuncAttributeMaxDynamicSharedMemorySize, SMEM_BYTES);

    lstm_persistent_kernel<<<NCTA, NTHR, SMEM_BYTES>>>(x, Wx, Wh, bias, out, write_hc);
}